// round 16
// baseline (speedup 1.0000x reference)
#include <cuda_runtime.h>
#include <math.h>
#include <stdint.h>

#define B  4
#define NN 65536
#define KK 16
#define DD 32
#define NP 16384

// scratch
__device__ float  g_pool_t[(size_t)B * NN * DD];    // 33.6 MB  [b][n][d]
__device__ float  g_interp_t[(size_t)B * NP * DD];  //  8.4 MB  [b][np][d]
__device__ float4 g_xyz4[(size_t)B * NN];           //  4.2 MB  padded xyz

#define TB1   (B * (NN / 128))     // 2048  transpose feat_pool tiles (32x128)
#define TB2   (B * (NP / 128))     // 512   transpose feat_interp tiles
#define XB    (B * NN / 1024)      // 256   xyz padding blocks
#define RELT  (B * NN * KK / 512)  // 8192  rel blocks total (512 pairs each)
#define RELA  2048                 // rel blocks run concurrently with kT
#define POOLB (B * (NP / 32))      // 2048  pool blocks
#define IB4   (B * (NN / 128))     // 2048  interp blocks (4 tiles each)
#define MIXB  ((RELT - RELA) + POOLB + IB4)  // 10240, period 5

__device__ __forceinline__ uint32_t smem_u32(const void* p) {
    uint32_t a;
    asm("{ .reg .u64 t; cvta.to.shared.u64 t, %1; cvt.u32.u64 %0, t; }"
        : "=r"(a) : "l"(p));
    return a;
}

// ============ kX: pad xyz [B*N,3] -> float4, 1024 pts/block ============
__global__ void __launch_bounds__(256) kX(const float* __restrict__ xyz) {
    __shared__ float s[3072];
    int tid = threadIdx.x;
    int p0 = blockIdx.x * 1024;
    const float4* src = (const float4*)(xyz + (size_t)p0 * 3);  // 768 float4
#pragma unroll
    for (int j = 0; j < 3; j++) {
        float4 v = __ldcs(&src[j * 256 + tid]);
        *(float4*)(s + (j * 256 + tid) * 4) = v;
    }
    __syncthreads();
#pragma unroll
    for (int j = 0; j < 4; j++) {
        int p = j * 256 + tid;
        g_xyz4[p0 + p] = make_float4(s[p * 3], s[p * 3 + 1], s[p * 3 + 2], 0.0f);
    }
}

// ============ kT: transpose [B,32,M] -> [B,M,32], 32x128 tiles, f4 both sides ===
__global__ void __launch_bounds__(256) kT(
    const float* __restrict__ feat_pool,
    const float* __restrict__ feat_interp)
{
    __shared__ float sm[32 * 132];    // 32 rows x 132 floats (pad 4)
    int tid = threadIdx.x;
    int tb = blockIdx.x;
    const float* in;
    float* outp;
    int M;
    if (tb < TB1) { in = feat_pool;   outp = g_pool_t;   M = NN; }
    else          { in = feat_interp; outp = g_interp_t; M = NP; tb -= TB1; }
    int mb = M / 128;
    int b  = tb / mb;
    int m0 = (tb - b * mb) * 128;

    // load: tile[d][m] for d 0..31, m 0..127, float4 over m
    {
        int d  = tid >> 3;          // 0..31
        int cq = tid & 7;           // f4 col base
        const float4* row = (const float4*)(in + ((size_t)(b * DD + d)) * M + m0);
#pragma unroll
        for (int j = 0; j < 4; j++) {
            int c4 = cq + 8 * j;    // 0..31 f4 within row
            float4 v = __ldcs(&row[c4]);
            *(float4*)(sm + d * 132 + c4 * 4) = v;
        }
    }
    __syncthreads();
    // store: out[m][4dq..4dq+3] = tile[4dq..4dq+3][m]
    {
#pragma unroll
        for (int j = 0; j < 4; j++) {
            int idx = tid + 256 * j;       // 0..1023
            int m  = idx >> 3;             // 0..127
            int dq = idx & 7;              // f4 within d
            float4 v = make_float4(sm[(4 * dq + 0) * 132 + m],
                                   sm[(4 * dq + 1) * 132 + m],
                                   sm[(4 * dq + 2) * 132 + m],
                                   sm[(4 * dq + 3) * 132 + m]);
            ((float4*)(outp + ((size_t)(b * M + m0 + m)) * DD))[dq] = v;
        }
    }
}

// rel block: 512 pairs, 2 pairs/thread, stage 20KB, TMA bulk store
__device__ __forceinline__ void do_rel(float* smem, int tid, int rb,
                                       const int* __restrict__ nidx,
                                       float* __restrict__ out_rel) {
    int pbase = rb * 512;
    int b   = pbase >> 20;              // N*K = 2^20
    int bb  = b << 16;
    int nkb = pbase & 0xFFFFF;
    int t2  = tid * 2;

    int2 ii = __ldcs((const int2*)(nidx + pbase + t2));
    float4 Q0 = __ldg(&g_xyz4[bb + ii.x]);
    float4 Q1 = __ldg(&g_xyz4[bb + ii.y]);
    // pairs (2t, 2t+1) share n since t2 is even and K=16
    float4 P  = __ldg(&g_xyz4[bb + ((nkb + t2) >> 4)]);

    float rx0 = P.x - Q0.x, ry0 = P.y - Q0.y, rz0 = P.z - Q0.z;
    float d0 = sqrtf(rx0 * rx0 + ry0 * ry0 + rz0 * rz0);
    float rx1 = P.x - Q1.x, ry1 = P.y - Q1.y, rz1 = P.z - Q1.z;
    float d1 = sqrtf(rx1 * rx1 + ry1 * ry1 + rz1 * rz1);

    float4* sp = (float4*)(smem + tid * 20);
    sp[0] = make_float4(d0, rx0, ry0, rz0);
    sp[1] = make_float4(P.x, P.y, P.z, Q0.x);
    sp[2] = make_float4(Q0.y, Q0.z, d1, rx1);
    sp[3] = make_float4(ry1, rz1, P.x, P.y);
    sp[4] = make_float4(P.z, Q1.x, Q1.y, Q1.z);
    __syncthreads();

    asm volatile("fence.proxy.async.shared::cta;" ::: "memory");
    if (tid == 0) {
        uint32_t sa = smem_u32(smem);
        float* gp = out_rel + (size_t)rb * 5120;
        asm volatile(
            "cp.async.bulk.global.shared::cta.bulk_group [%0], [%1], %2;"
            :: "l"(gp), "r"(sa), "n"(20480) : "memory");
        asm volatile("cp.async.bulk.commit_group;" ::: "memory");
        asm volatile("cp.async.bulk.wait_group.read 0;" ::: "memory");
    }
    __syncthreads();
}

// ============ kRelA: rel blocks 0..RELA-1 (runs concurrent with kT) ============
__global__ void __launch_bounds__(256) kRelA(
    const int* __restrict__ nidx,
    float* __restrict__ out_rel)
{
    __shared__ __align__(16) float smem[5120];
    do_rel(smem, threadIdx.x, blockIdx.x, nidx, out_rel);
}

// ============ kMix: remaining rel + pool + interp, interleaved (bid%5) ============
__global__ void __launch_bounds__(256) kMix(
    const int* __restrict__ nidx,
    const int* __restrict__ pool_idx,
    const int* __restrict__ interp_idx,
    float* __restrict__ out_rel,
    float* __restrict__ out_pool,
    float* __restrict__ out_interp)
{
    __shared__ __align__(16) float smem[5120];   // 20 KB
    int bid = blockIdx.x;
    int tid = threadIdx.x;
    int r = bid % 5;
    int g = bid / 5;          // 0..2047

    if (r == 0) {
        // -------- gather-max pooling --------
        float (*tile)[33] = (float (*)[33])smem;
        int lane = tid & 31, w = tid >> 5;
        int row  = w * 4 + (lane >> 3);
        int dv   = lane & 7;
        int b   = g / (NP / 32);
        int np0 = (g - b * (NP / 32)) * 32;
        const int* ip = pool_idx + (b * NP + np0 + row) * KK;
        const float* basep = g_pool_t + (size_t)b * NN * DD;

        float4 m = make_float4(-INFINITY, -INFINITY, -INFINITY, -INFINITY);
#pragma unroll
        for (int kc = 0; kc < 4; kc++) {
            int4 q = __ldcs((const int4*)ip + kc);
            int qq[4] = {q.x, q.y, q.z, q.w};
#pragma unroll
            for (int j = 0; j < 4; j++) {
                float4 v = *(const float4*)(basep + qq[j] * DD + dv * 4);
                m.x = fmaxf(m.x, v.x); m.y = fmaxf(m.y, v.y);
                m.z = fmaxf(m.z, v.z); m.w = fmaxf(m.w, v.w);
            }
        }
        tile[row][dv * 4 + 0] = m.x;
        tile[row][dv * 4 + 1] = m.y;
        tile[row][dv * 4 + 2] = m.z;
        tile[row][dv * 4 + 3] = m.w;
        __syncthreads();
#pragma unroll
        for (int rr = 0; rr < 4; rr++) {
            int d = w + 8 * rr;
            __stcs(&out_pool[(size_t)(b * DD + d) * NP + np0 + lane], tile[lane][d]);
        }
    } else if (r == 2) {
        // -------- nearest interpolation: 4 tiles / block --------
        float (*tile)[33] = (float (*)[33])smem;
        int lane = tid & 31, w = tid >> 5;
        int row  = w * 4 + (lane >> 3);
        int dv   = lane & 7;
        int b  = g / (NN / 128);
        int u0 = (g - b * (NN / 128)) * 128;

        float4 v[4];
#pragma unroll
        for (int it = 0; it < 4; it++) {
            int i = __ldg(&interp_idx[b * NN + u0 + it * 32 + row]);
            v[it] = *(const float4*)(g_interp_t + ((size_t)(b * NP + i)) * DD + dv * 4);
        }
#pragma unroll
        for (int it = 0; it < 4; it++) {
            tile[it * 32 + row][dv * 4 + 0] = v[it].x;
            tile[it * 32 + row][dv * 4 + 1] = v[it].y;
            tile[it * 32 + row][dv * 4 + 2] = v[it].z;
            tile[it * 32 + row][dv * 4 + 3] = v[it].w;
        }
        __syncthreads();
#pragma unroll
        for (int it = 0; it < 4; it++) {
#pragma unroll
            for (int rr = 0; rr < 4; rr++) {
                int d = w + 8 * rr;
                __stcs(&out_interp[(size_t)(b * DD + d) * NN + u0 + it * 32 + lane],
                       tile[it * 32 + lane][d]);
            }
        }
    } else {
        // -------- rel: blocks RELA..RELT-1 --------
        int sub = (r == 1) ? 0 : (r == 3) ? 1 : 2;
        do_rel(smem, tid, RELA + g * 3 + sub, nidx, out_rel);
    }
}

extern "C" void kernel_launch(void* const* d_in, const int* in_sizes, int n_in,
                              void* d_out, int out_size) {
    const float* xyz         = (const float*)d_in[0];   // [B,N,3]
    const int*   neigh_idx   = (const int*)  d_in[1];   // [B,N,K]
    const float* feat_pool   = (const float*)d_in[2];   // [B,32,N,1]
    const int*   pool_idx    = (const int*)  d_in[3];   // [B,Np,K]
    const float* feat_interp = (const float*)d_in[4];   // [B,32,Np,1]
    const int*   interp_idx  = (const int*)  d_in[5];   // [B,N,1]

    float* out = (float*)d_out;
    float* out_rel    = out;                                // B*N*K*10
    float* out_pool   = out + (size_t)B * NN * KK * 10;     // B*32*Np
    float* out_interp = out_pool + (size_t)B * DD * NP;     // B*32*N

    // one-time side stream + events (host-side objects; no device allocs)
    static cudaStream_t s2 = nullptr;
    static cudaEvent_t evFork = nullptr, evT = nullptr;
    if (s2 == nullptr) {
        cudaStreamCreateWithFlags(&s2, cudaStreamNonBlocking);
        cudaEventCreateWithFlags(&evFork, cudaEventDisableTiming);
        cudaEventCreateWithFlags(&evT, cudaEventDisableTiming);
    }

    // fork: kT runs parallel to kX + kRelA
    cudaEventRecord(evFork, 0);
    cudaStreamWaitEvent(s2, evFork, 0);

    kT<<<TB1 + TB2, 256, 0, s2>>>(feat_pool, feat_interp);
    cudaEventRecord(evT, s2);

    kX   <<<XB, 256>>>(xyz);
    kRelA<<<RELA, 256>>>(neigh_idx, out_rel);

    // kMix needs kT's transposed scratch
    cudaStreamWaitEvent(0, evT, 0);
    kMix<<<MIXB, 256>>>(neigh_idx, pool_idx, interp_idx,
                        out_rel, out_pool, out_interp);
}